// round 1
// baseline (speedup 1.0000x reference)
#include <cuda_runtime.h>
#include <cstdint>

// MyConvNet: B=2048, x[ B,1,28,28 ]
//  conv1 1->64 3x3 -> 26x26 ; maxpool 3/2 -> 12x12 ; relu
//  conv2 64->64 3x3 -> 10x10 ; maxpool 3/2 -> 4x4  ; relu
//  conv3 64->10 4x4 -> 1x1   ; out [B,10]
//
// One CTA per image, everything fused in shared memory.

typedef unsigned long long ull;

__device__ __forceinline__ ull pack2(float lo, float hi) {
    ull v;
    asm("mov.b64 %0, {%1, %2};" : "=l"(v) : "f"(lo), "f"(hi));
    return v;
}
__device__ __forceinline__ void unpack2(ull v, float& lo, float& hi) {
    asm("mov.b64 {%0, %1}, %2;" : "=f"(lo), "=f"(hi) : "l"(v));
}
__device__ __forceinline__ void fma2(ull& d, ull a, ull b) {
    // packed f32x2 fma (Blackwell): d = a*b + d elementwise on 2 floats
    asm("fma.rn.f32x2 %0, %1, %2, %0;" : "+l"(d) : "l"(a), "l"(b));
}

// ---- shared memory layout (in floats) ----
// x_s   :     0 .. 784
// w1_s  :   784 .. 1360   (64*9)
// b1_s  :  1360 .. 1424
// b2_s  :  1424 .. 1488
// h1_s  :  1488 .. 10768  (64 * 145, stride-145 pad, 12x12 per channel)
// c2_s  : 10768 .. 15952  (64 * 81, conv2 at the 9x9 positions pool2 needs)
// h2_s  : 15952 .. 16976  (64 * 16)
// w2t   : 16976 .. 56144  (576 * 68, w2 transposed [k][oc], pad 68 for
//                          16B-aligned float4 loads + conflict control)
#define SMEM_FLOATS 56144
#define SMEM_BYTES  (SMEM_FLOATS * 4)

__global__ void __launch_bounds__(256, 1)
convnet_kernel(const float* __restrict__ x,
               const float* __restrict__ w1, const float* __restrict__ b1,
               const float* __restrict__ w2, const float* __restrict__ b2,
               const float* __restrict__ w3, const float* __restrict__ b3,
               float* __restrict__ out)
{
    extern __shared__ float sm[];
    float* x_s  = sm;
    float* w1_s = sm + 784;
    float* b1_s = sm + 1360;
    float* b2_s = sm + 1424;
    float* h1_s = sm + 1488;
    float* c2_s = sm + 10768;
    float* h2_s = sm + 15952;
    float* w2t  = sm + 16976;

    const int tid = threadIdx.x;
    const int img = blockIdx.x;

    // ---------------- Phase 0: loads ----------------
    {
        const float* xg = x + img * 784;
        for (int i = tid; i < 784; i += 256) x_s[i] = xg[i];
        for (int i = tid; i < 576; i += 256) w1_s[i] = w1[i];
        if (tid < 64) { b1_s[tid] = b1[tid]; b2_s[tid] = b2[tid]; }
        // w2 global layout: [oc][ic][3][3] = [oc][k], k = ic*9 + r*3 + c
        // store transposed: w2t[k*68 + oc]
        for (int i = tid; i < 64 * 576; i += 256) {
            int oc = i / 576;
            int k  = i - oc * 576;
            w2t[k * 68 + oc] = w2[i];
        }
    }
    __syncthreads();

    // ------- Phase 1: conv1 + maxpool(3,2) + relu -> h1 [64][12x12] -------
    {
        const int c = tid & 63;   // channel
        const int g = tid >> 6;   // 0..3 position group (warp-uniform g)
        float wr[9];
        #pragma unroll
        for (int j = 0; j < 9; j++) wr[j] = w1_s[c * 9 + j];
        const float bc = b1_s[c];

        for (int p = g; p < 144; p += 4) {
            const int py = p / 12, px = p - py * 12;
            const float* xp = x_s + (2 * py) * 28 + 2 * px;
            float in[5][5];
            #pragma unroll
            for (int r = 0; r < 5; r++)
                #pragma unroll
                for (int cc = 0; cc < 5; cc++) in[r][cc] = xp[r * 28 + cc];
            float m = -3.0e38f;
            #pragma unroll
            for (int dy = 0; dy < 3; dy++)
                #pragma unroll
                for (int dx = 0; dx < 3; dx++) {
                    float s = 0.f;
                    #pragma unroll
                    for (int r = 0; r < 3; r++)
                        #pragma unroll
                        for (int cc = 0; cc < 3; cc++)
                            s = fmaf(wr[r * 3 + cc], in[dy + r][dx + cc], s);
                    m = fmaxf(m, s);
                }
            h1_s[c * 145 + p] = fmaxf(m + bc, 0.f);
        }
    }
    __syncthreads();

    // ------- Phase 2: conv2 at 9x9 positions (all pool2 needs) -------
    // outputs: c2[oc][pos], oc in 0..63, pos = y*9 + x, y,x in 0..8
    // thread tile: 8 output channels (as 4 f32x2 pairs) x 3 columns
    if (tid < 216) {
        const int ocb = tid & 7;         // 0..7 -> oc0 = 8*ocb
        const int s   = tid >> 3;        // 0..26
        const int oc0 = ocb * 8;
        const int yy  = s / 3;           // 0..8
        const int x0  = (s - yy * 3) * 3; // 0,3,6

        ull acc[3][4];
        #pragma unroll
        for (int j = 0; j < 3; j++)
            #pragma unroll
            for (int q = 0; q < 4; q++) acc[j][q] = 0ull;

        for (int ic = 0; ic < 64; ic++) {
            const float* hrow  = h1_s + ic * 145 + yy * 12 + x0;
            const float* wbase = w2t + (ic * 9) * 68 + oc0;
            #pragma unroll
            for (int r = 0; r < 3; r++) {
                ull ap[5];
                #pragma unroll
                for (int q = 0; q < 5; q++) {
                    float a = hrow[r * 12 + q];
                    ap[q] = pack2(a, a);
                }
                #pragma unroll
                for (int cn = 0; cn < 3; cn++) {
                    const float4 wv0 = *reinterpret_cast<const float4*>(wbase + (r * 3 + cn) * 68);
                    const float4 wv1 = *reinterpret_cast<const float4*>(wbase + (r * 3 + cn) * 68 + 4);
                    const ull w01 = pack2(wv0.x, wv0.y);
                    const ull w23 = pack2(wv0.z, wv0.w);
                    const ull w45 = pack2(wv1.x, wv1.y);
                    const ull w67 = pack2(wv1.z, wv1.w);
                    #pragma unroll
                    for (int j = 0; j < 3; j++) {
                        fma2(acc[j][0], w01, ap[cn + j]);
                        fma2(acc[j][1], w23, ap[cn + j]);
                        fma2(acc[j][2], w45, ap[cn + j]);
                        fma2(acc[j][3], w67, ap[cn + j]);
                    }
                }
            }
        }
        // store with bias
        #pragma unroll
        for (int j = 0; j < 3; j++) {
            const int pos = yy * 9 + x0 + j;
            #pragma unroll
            for (int q = 0; q < 4; q++) {
                float lo, hi;
                unpack2(acc[j][q], lo, hi);
                const int oc = oc0 + 2 * q;
                c2_s[oc * 81 + pos]       = lo + b2_s[oc];
                c2_s[(oc + 1) * 81 + pos] = hi + b2_s[oc + 1];
            }
        }
    }
    __syncthreads();

    // ------- Phase 3: maxpool2(3,2) + relu -> h2 [64][4][4] -------
    for (int i = tid; i < 1024; i += 256) {
        const int oc = i >> 4;
        const int p  = i & 15;
        const int j  = p >> 2, ii = p & 3;
        const float* base = c2_s + oc * 81 + (2 * j) * 9 + 2 * ii;
        float m = base[0];
        #pragma unroll
        for (int dy = 0; dy < 3; dy++)
            #pragma unroll
            for (int dx = 0; dx < 3; dx++) m = fmaxf(m, base[dy * 9 + dx]);
        h2_s[oc * 16 + p] = fmaxf(m, 0.f);
    }
    __syncthreads();

    // ------- Phase 4: conv3 (dot over 64*4*4 = 1024) -> out[img][10] -------
    {
        const int wid  = tid >> 5;
        const int lane = tid & 31;
        #pragma unroll
        for (int t = 0; t < 2; t++) {
            const int o = wid + t * 8;
            if (o < 10) {
                const float* wp = w3 + o * 1024;
                float sres = 0.f;
                #pragma unroll 8
                for (int k = lane; k < 1024; k += 32)
                    sres = fmaf(__ldg(wp + k), h2_s[k], sres);
                #pragma unroll
                for (int off = 16; off > 0; off >>= 1)
                    sres += __shfl_down_sync(0xffffffffu, sres, off);
                if (lane == 0) out[img * 10 + o] = sres + b3[o];
            }
        }
    }
}

extern "C" void kernel_launch(void* const* d_in, const int* in_sizes, int n_in,
                              void* d_out, int out_size)
{
    const float* x  = (const float*)d_in[0];
    const float* w1 = (const float*)d_in[1];
    const float* b1 = (const float*)d_in[2];
    const float* w2 = (const float*)d_in[3];
    const float* b2 = (const float*)d_in[4];
    const float* w3 = (const float*)d_in[5];
    const float* b3 = (const float*)d_in[6];
    float* out = (float*)d_out;

    const int B = in_sizes[0] / 784;

    // idempotent, host-side, capture-safe
    cudaFuncSetAttribute(convnet_kernel,
                         cudaFuncAttributeMaxDynamicSharedMemorySize, SMEM_BYTES);

    convnet_kernel<<<B, 256, SMEM_BYTES>>>(x, w1, b1, w2, b2, w3, b3, out);
}

// round 2
// speedup vs baseline: 1.2320x; 1.2320x over previous
#include <cuda_runtime.h>
#include <cstdint>

// MyConvNet fused kernel, one CTA per image, 288 threads.
//  conv1 1->64 3x3 -> 26x26 ; maxpool 3/2 -> 12x12 ; relu
//  conv2 64->64 3x3 -> 10x10 ; maxpool 3/2 -> 4x4  ; relu
//  conv3 64->10 4x4 -> 1x1   ; out [B,10]

typedef unsigned long long ull;

__device__ __forceinline__ ull pack2(float lo, float hi) {
    ull v;
    asm("mov.b64 %0, {%1, %2};" : "=l"(v) : "f"(lo), "f"(hi));
    return v;
}
__device__ __forceinline__ void unpack2(ull v, float& lo, float& hi) {
    asm("mov.b64 {%0, %1}, %2;" : "=f"(lo), "=f"(hi) : "l"(v));
}
__device__ __forceinline__ void fma2(ull& d, ull a, ull b) {
    asm("fma.rn.f32x2 %0, %1, %2, %0;" : "+l"(d) : "l"(a), "l"(b));
}
__device__ __forceinline__ void add2(ull& d, ull a) {
    asm("add.rn.f32x2 %0, %0, %1;" : "+l"(d) : "l"(a));
}

// ---- shared memory layout (float offsets) ----
// x_s   :     0 .. 784
// w1_s  :   784 .. 1360   (64*9)
// b1_s  :  1360 .. 1424
// b2_s  :  1424 .. 1488
// h1_s  :  1488 .. 10768  (64 * 145; 12x12 per channel, stride 145)
// c2_s  : 10768 .. 15952  (64 * 81; conv2 at the 9x9 positions pool2 needs)
// h2_s  : 15952 .. 16976  (64 * 16)
// w2t   : 16976 .. 56144  (576 * 68; w2 transposed [k][oc], row pad 68)
//         (w2t region is reused as the phase-2 reduction scratch)
#define SMEM_FLOATS 56144
#define SMEM_BYTES  (SMEM_FLOATS * 4)
#define NT 288

__global__ void __launch_bounds__(NT, 1)
convnet_kernel(const float* __restrict__ x,
               const float* __restrict__ w1, const float* __restrict__ b1,
               const float* __restrict__ w2, const float* __restrict__ b2,
               const float* __restrict__ w3, const float* __restrict__ b3,
               float* __restrict__ out)
{
    extern __shared__ float sm[];
    float* x_s  = sm;
    float* w1_s = sm + 784;
    float* b1_s = sm + 1360;
    float* b2_s = sm + 1424;
    float* h1_s = sm + 1488;
    float* c2_s = sm + 10768;
    float* h2_s = sm + 15952;
    float* w2t  = sm + 16976;

    const int tid  = threadIdx.x;
    const int img  = blockIdx.x;
    const int wid  = tid >> 5;
    const int lane = tid & 31;

    // ---------------- Phase 0: loads ----------------
    {
        const float* xg = x + img * 784;
        for (int i = tid; i < 784; i += NT) x_s[i] = xg[i];
        for (int i = tid; i < 576; i += NT) w1_s[i] = w1[i];
        if (tid < 64) { b1_s[tid] = b1[tid]; b2_s[tid] = b2[tid]; }

        // w2 transpose: w2t[k*68 + oc] = w2[oc*576 + k]
        // warp handles a 4-oc strip; lane = (ol, kl) -> conflict-free STS,
        // 32B-coalesced LDG groups.
        const int ol = lane >> 3;   // 0..3
        const int kl = lane & 7;    // 0..7
        for (int strip = wid; strip < 16; strip += 9) {
            const int oc = strip * 4 + ol;
            const float* src = w2 + oc * 576;
            #pragma unroll 4
            for (int j = 0; j < 72; j++) {
                const int k = kl + 8 * j;
                w2t[k * 68 + oc] = __ldg(src + k);
            }
        }
    }
    __syncthreads();

    // ------- Phase 1: conv1 + maxpool(3,2) + relu -> h1 [64][12x12] -------
    // Each task computes a PAIR of adjacent pool outputs via packed f32x2.
    // tasks: 64 ch * 72 pairs = 4608
    for (int t = tid; t < 4608; t += NT) {
        const int ch  = t & 63;
        const int pr  = t >> 6;            // 0..71
        const int py  = pr / 6;
        const int px0 = (pr - py * 6) * 2; // 0,2,4,6,8,10

        float wr[9];
        #pragma unroll
        for (int j = 0; j < 9; j++) wr[j] = w1_s[ch * 9 + j];
        const float bc = b1_s[ch];

        const float* xp = x_s + (2 * py) * 28 + 2 * px0;
        // packed activation pairs: pa[r][c] = (in[r][c], in[r][c+2])
        ull pa[5][5];
        #pragma unroll
        for (int r = 0; r < 5; r++) {
            float row[7];
            #pragma unroll
            for (int c = 0; c < 7; c++) row[c] = xp[r * 28 + c];
            #pragma unroll
            for (int c = 0; c < 5; c++) pa[r][c] = pack2(row[c], row[c + 2]);
        }

        float m0 = -3.0e38f, m1 = -3.0e38f;
        #pragma unroll
        for (int dy = 0; dy < 3; dy++)
            #pragma unroll
            for (int dx = 0; dx < 3; dx++) {
                ull s2 = 0ull;
                #pragma unroll
                for (int r = 0; r < 3; r++)
                    #pragma unroll
                    for (int cc = 0; cc < 3; cc++)
                        fma2(s2, pack2(wr[r * 3 + cc], wr[r * 3 + cc]),
                             pa[dy + r][dx + cc]);
                float s0, s1;
                unpack2(s2, s0, s1);
                m0 = fmaxf(m0, s0);
                m1 = fmaxf(m1, s1);
            }
        h1_s[ch * 145 + py * 12 + px0]     = fmaxf(m0 + bc, 0.f);
        h1_s[ch * 145 + py * 12 + px0 + 1] = fmaxf(m1 + bc, 0.f);
    }
    __syncthreads();

    // ------- Phase 2: conv2 at 9x9 positions, 4-way ic split -------
    // thread tile: 8 output channels x 9 positions (one full output row),
    // ic range of 16 per group. 4 groups * 72 threads = 288.
    const int group = tid / 72;         // 0..3
    const int wi    = tid - group * 72; // 0..71
    const int ocb   = wi & 7;           // 0..7  -> oc0 = 8*ocb
    const int yy    = wi >> 3;          // 0..8  output row
    const int oc0   = ocb * 8;

    ull acc[9][4];
    #pragma unroll
    for (int j = 0; j < 9; j++)
        #pragma unroll
        for (int q = 0; q < 4; q++) acc[j][q] = 0ull;

    {
        const int ic0 = group * 16;
        #pragma unroll 1
        for (int ic = ic0; ic < ic0 + 16; ic++) {
            const float* hrow = h1_s + ic * 145 + yy * 12;
            const int kbase = ic * 9;
            #pragma unroll
            for (int r = 0; r < 3; r++) {
                ull ap[11];
                #pragma unroll
                for (int c = 0; c < 11; c++) {
                    const float a = hrow[r * 12 + c];
                    ap[c] = pack2(a, a);
                }
                #pragma unroll
                for (int cn = 0; cn < 3; cn++) {
                    const ulonglong2* wp = reinterpret_cast<const ulonglong2*>(
                        w2t + (kbase + r * 3 + cn) * 68 + oc0);
                    const ulonglong2 wA = wp[0];
                    const ulonglong2 wB = wp[1];
                    #pragma unroll
                    for (int j = 0; j < 9; j++) {
                        fma2(acc[j][0], wA.x, ap[cn + j]);
                        fma2(acc[j][1], wA.y, ap[cn + j]);
                        fma2(acc[j][2], wB.x, ap[cn + j]);
                        fma2(acc[j][3], wB.y, ap[cn + j]);
                    }
                }
            }
        }
    }
    __syncthreads();  // all groups done reading w2t -> safe to reuse as scratch

    // partials -> scratch (aliases w2t region), then packed reduction
    {
        ull* scratch = reinterpret_cast<ull*>(w2t);
        #pragma unroll
        for (int j = 0; j < 9; j++) {
            const int pos = yy * 9 + j;
            #pragma unroll
            for (int q = 0; q < 4; q++) {
                const int p = ocb * 4 + q;  // oc pair index 0..31
                scratch[(p * 81 + pos) * 4 + group + p] = acc[j][q];
            }
        }
        __syncthreads();
        for (int u = tid; u < 2592; u += NT) {
            const int p   = u / 81;
            const int pos = u - p * 81;
            const ull* s  = scratch + u * 4 + p;
            ull v = s[0];
            add2(v, s[1]);
            add2(v, s[2]);
            add2(v, s[3]);
            float lo, hi;
            unpack2(v, lo, hi);
            const int oc = 2 * p;
            c2_s[oc * 81 + pos]      = lo + b2_s[oc];
            c2_s[oc * 81 + 81 + pos] = hi + b2_s[oc + 1];
        }
    }
    __syncthreads();

    // ------- Phase 3: maxpool2(3,2) + relu -> h2 [64][16] -------
    for (int i = tid; i < 1024; i += NT) {
        const int oc = i >> 4;
        const int p  = i & 15;
        const int j  = p >> 2, ii = p & 3;
        const float* base = c2_s + oc * 81 + (2 * j) * 9 + 2 * ii;
        float m = base[0];
        #pragma unroll
        for (int dy = 0; dy < 3; dy++)
            #pragma unroll
            for (int dx = 0; dx < 3; dx++) m = fmaxf(m, base[dy * 9 + dx]);
        h2_s[oc * 16 + p] = fmaxf(m, 0.f);
    }
    __syncthreads();

    // ------- Phase 4: conv3 (10 dots over 1024) -------
    for (int o = wid; o < 10; o += 9) {
        const float* wp = w3 + (o << 10);
        float sres = 0.f;
        #pragma unroll 8
        for (int k = lane; k < 1024; k += 32)
            sres = fmaf(__ldg(wp + k), h2_s[k], sres);
        #pragma unroll
        for (int off = 16; off > 0; off >>= 1)
            sres += __shfl_down_sync(0xffffffffu, sres, off);
        if (lane == 0) out[img * 10 + o] = sres + b3[o];
    }
}

extern "C" void kernel_launch(void* const* d_in, const int* in_sizes, int n_in,
                              void* d_out, int out_size)
{
    const float* x  = (const float*)d_in[0];
    const float* w1 = (const float*)d_in[1];
    const float* b1 = (const float*)d_in[2];
    const float* w2 = (const float*)d_in[3];
    const float* b2 = (const float*)d_in[4];
    const float* w3 = (const float*)d_in[5];
    const float* b3 = (const float*)d_in[6];
    float* out = (float*)d_out;

    const int B = in_sizes[0] / 784;

    cudaFuncSetAttribute(convnet_kernel,
                         cudaFuncAttributeMaxDynamicSharedMemorySize, SMEM_BYTES);

    convnet_kernel<<<B, NT, SMEM_BYTES>>>(x, w1, b1, w2, b2, w3, b3, out);
}

// round 3
// speedup vs baseline: 1.6347x; 1.3268x over previous
#include <cuda_runtime.h>
#include <cstdint>

// MyConvNet fused kernel, one CTA per image, 576 threads (18 warps).
//  conv1 1->64 3x3 -> 26x26 ; maxpool 3/2 -> 12x12 ; relu
//  conv2 64->64 3x3 -> 10x10 ; maxpool 3/2 -> 4x4  ; relu
//  conv3 64->10 4x4 -> 1x1   ; out [B,10]

typedef unsigned long long ull;

__device__ __forceinline__ ull pack2(float lo, float hi) {
    ull v;
    asm("mov.b64 %0, {%1, %2};" : "=l"(v) : "f"(lo), "f"(hi));
    return v;
}
__device__ __forceinline__ void unpack2(ull v, float& lo, float& hi) {
    asm("mov.b64 {%0, %1}, %2;" : "=f"(lo), "=f"(hi) : "l"(v));
}
__device__ __forceinline__ void fma2(ull& d, ull a, ull b) {
    asm("fma.rn.f32x2 %0, %1, %2, %0;" : "+l"(d) : "l"(a), "l"(b));
}
__device__ __forceinline__ void add2(ull& d, ull a) {
    asm("add.rn.f32x2 %0, %0, %1;" : "+l"(d) : "l"(a));
}

// ---- shared memory layout (float offsets) ----
// x_s   :     0 .. 784
// w1_s  :   784 .. 1360   (64*9)
// b1_s  :  1360 .. 1424
// b2_s  :  1424 .. 1488
// h1_s  :  1488 .. 10768  (64 * 145; 12x12 per channel, stride 145)
// c2_s  : 10768 .. 15952  (64 * 81; conv2 at the 9x9 positions pool2 needs)
// h2_s  : 15952 .. 16976  (64 * 16)
// w2t   : 16976 .. 56144  (576 * 68; w2 transposed [k][oc], row pad 68)
//         (w2t region reused as phase-2 reduction scratch)
#define SMEM_FLOATS 56144
#define SMEM_BYTES  (SMEM_FLOATS * 4)
#define NT 576

__global__ void __launch_bounds__(NT, 1)
convnet_kernel(const float* __restrict__ x,
               const float* __restrict__ w1, const float* __restrict__ b1,
               const float* __restrict__ w2, const float* __restrict__ b2,
               const float* __restrict__ w3, const float* __restrict__ b3,
               float* __restrict__ out)
{
    extern __shared__ float sm[];
    float* x_s  = sm;
    float* w1_s = sm + 784;
    float* b1_s = sm + 1360;
    float* b2_s = sm + 1424;
    float* h1_s = sm + 1488;
    float* c2_s = sm + 10768;
    float* h2_s = sm + 15952;
    float* w2t  = sm + 16976;

    const int tid  = threadIdx.x;
    const int img  = blockIdx.x;
    const int wid  = tid >> 5;
    const int lane = tid & 31;

    // ---------------- Phase 0: loads ----------------
    {
        const float* xg = x + img * 784;
        for (int i = tid; i < 784; i += NT) x_s[i] = xg[i];
        if (tid < 576) w1_s[tid] = w1[tid];
        if (tid < 64) { b1_s[tid] = b1[tid]; b2_s[tid] = b2[tid]; }

        // w2 transpose: w2t[k*68 + oc] = w2[oc*576 + k]
        // warp handles a 4-oc strip; lane = (ol, kl) -> conflict-free STS,
        // 32B-coalesced LDG groups.
        const int ol = lane >> 3;   // 0..3
        const int kl = lane & 7;    // 0..7
        if (wid < 16) {
            const int oc = wid * 4 + ol;
            const float* src = w2 + oc * 576;
            #pragma unroll 4
            for (int j = 0; j < 72; j++) {
                const int k = kl + 8 * j;
                w2t[k * 68 + oc] = __ldg(src + k);
            }
        }
    }
    __syncthreads();

    // ------- Phase 1: conv1 + maxpool(3,2) + relu -> h1 [64][12x12] -------
    // Each task: a PAIR of adjacent pool outputs via packed f32x2.
    // 64 ch * 72 pairs = 4608 tasks; ch fixed per thread -> weights hoisted.
    {
        const int ch = tid & 63;
        const int g0 = tid >> 6;   // 0..8
        float wr[9];
        #pragma unroll
        for (int j = 0; j < 9; j++) wr[j] = w1_s[ch * 9 + j];
        const float bc = b1_s[ch];

        #pragma unroll 1
        for (int it = 0; it < 8; it++) {
            const int pr  = g0 + 9 * it;       // 0..71
            const int py  = pr / 6;
            const int px0 = (pr - py * 6) * 2; // 0,2,4,6,8,10

            const float* xp = x_s + (2 * py) * 28 + 2 * px0;
            // packed activation pairs: pa[r][c] = (in[r][c], in[r][c+2])
            ull pa[5][5];
            #pragma unroll
            for (int r = 0; r < 5; r++) {
                float row[7];
                #pragma unroll
                for (int c = 0; c < 7; c++) row[c] = xp[r * 28 + c];
                #pragma unroll
                for (int c = 0; c < 5; c++) pa[r][c] = pack2(row[c], row[c + 2]);
            }

            float m0 = -3.0e38f, m1 = -3.0e38f;
            #pragma unroll
            for (int dy = 0; dy < 3; dy++)
                #pragma unroll
                for (int dx = 0; dx < 3; dx++) {
                    ull s2 = 0ull;
                    #pragma unroll
                    for (int r = 0; r < 3; r++)
                        #pragma unroll
                        for (int cc = 0; cc < 3; cc++)
                            fma2(s2, pack2(wr[r * 3 + cc], wr[r * 3 + cc]),
                                 pa[dy + r][dx + cc]);
                    float s0, s1;
                    unpack2(s2, s0, s1);
                    m0 = fmaxf(m0, s0);
                    m1 = fmaxf(m1, s1);
                }
            h1_s[ch * 145 + py * 12 + px0]     = fmaxf(m0 + bc, 0.f);
            h1_s[ch * 145 + py * 12 + px0 + 1] = fmaxf(m1 + bc, 0.f);
        }
    }
    __syncthreads();

    // ------- Phase 2: conv2 at 9x9 positions, 4-way ic split -------
    // thread tile: 4 output channels x 9 positions (one output row),
    // 16 ic per group. 4 groups * 144 threads = 576.
    const int group = tid / 144;          // 0..3
    const int wi    = tid - group * 144;  // 0..143
    const int ocb   = wi & 15;            // 0..15 -> oc0 = 4*ocb
    const int yy    = wi >> 4;            // 0..8  output row
    const int oc0   = ocb * 4;

    ull acc[9][2];
    #pragma unroll
    for (int j = 0; j < 9; j++) { acc[j][0] = 0ull; acc[j][1] = 0ull; }

    {
        const int ic0 = group * 16;
        #pragma unroll 1
        for (int ic = ic0; ic < ic0 + 16; ic++) {
            const float* hrow = h1_s + ic * 145 + yy * 12;
            const int kbase = ic * 9;
            #pragma unroll
            for (int r = 0; r < 3; r++) {
                ull ap[11];
                #pragma unroll
                for (int c = 0; c < 11; c++) {
                    const float a = hrow[r * 12 + c];
                    ap[c] = pack2(a, a);
                }
                #pragma unroll
                for (int cn = 0; cn < 3; cn++) {
                    const ulonglong2 wv = *reinterpret_cast<const ulonglong2*>(
                        w2t + (kbase + r * 3 + cn) * 68 + oc0);
                    #pragma unroll
                    for (int j = 0; j < 9; j++) {
                        fma2(acc[j][0], wv.x, ap[cn + j]);
                        fma2(acc[j][1], wv.y, ap[cn + j]);
                    }
                }
            }
        }
    }
    __syncthreads();  // all groups done reading w2t -> safe to reuse as scratch

    // partials -> scratch (aliases w2t region), then packed reduction
    {
        ull* scratch = reinterpret_cast<ull*>(w2t);
        #pragma unroll
        for (int j = 0; j < 9; j++) {
            const int pos = yy * 9 + j;
            #pragma unroll
            for (int q = 0; q < 2; q++) {
                const int p = ocb * 2 + q;  // oc pair index 0..31
                scratch[(p * 81 + pos) * 4 + group + p] = acc[j][q];
            }
        }
        __syncthreads();
        for (int u = tid; u < 2592; u += NT) {
            const int p   = u / 81;
            const int pos = u - p * 81;
            const ull* s  = scratch + u * 4 + p;
            ull v = s[0];
            add2(v, s[1]);
            add2(v, s[2]);
            add2(v, s[3]);
            float lo, hi;
            unpack2(v, lo, hi);
            const int oc = 2 * p;
            c2_s[oc * 81 + pos]      = lo + b2_s[oc];
            c2_s[oc * 81 + 81 + pos] = hi + b2_s[oc + 1];
        }
    }
    __syncthreads();

    // ------- Phase 3: maxpool2(3,2) + relu -> h2 [64][16] -------
    for (int i = tid; i < 1024; i += NT) {
        const int oc = i >> 4;
        const int p  = i & 15;
        const int j  = p >> 2, ii = p & 3;
        const float* base = c2_s + oc * 81 + (2 * j) * 9 + 2 * ii;
        float m = base[0];
        #pragma unroll
        for (int dy = 0; dy < 3; dy++)
            #pragma unroll
            for (int dx = 0; dx < 3; dx++) m = fmaxf(m, base[dy * 9 + dx]);
        h2_s[oc * 16 + p] = fmaxf(m, 0.f);
    }
    __syncthreads();

    // ------- Phase 4: conv3 (10 dots over 1024) -------
    if (wid < 10) {
        const float* wp = w3 + (wid << 10);
        float sres = 0.f;
        #pragma unroll 8
        for (int k = lane; k < 1024; k += 32)
            sres = fmaf(__ldg(wp + k), h2_s[k], sres);
        #pragma unroll
        for (int off = 16; off > 0; off >>= 1)
            sres += __shfl_down_sync(0xffffffffu, sres, off);
        if (lane == 0) out[img * 10 + wid] = sres + b3[wid];
    }
}

extern "C" void kernel_launch(void* const* d_in, const int* in_sizes, int n_in,
                              void* d_out, int out_size)
{
    const float* x  = (const float*)d_in[0];
    const float* w1 = (const float*)d_in[1];
    const float* b1 = (const float*)d_in[2];
    const float* w2 = (const float*)d_in[3];
    const float* b2 = (const float*)d_in[4];
    const float* w3 = (const float*)d_in[5];
    const float* b3 = (const float*)d_in[6];
    float* out = (float*)d_out;

    const int B = in_sizes[0] / 784;

    cudaFuncSetAttribute(convnet_kernel,
                         cudaFuncAttributeMaxDynamicSharedMemorySize, SMEM_BYTES);

    convnet_kernel<<<B, NT, SMEM_BYTES>>>(x, w1, b1, w2, b2, w3, b3, out);
}